// round 10
// baseline (speedup 1.0000x reference)
#include <cuda_runtime.h>
#include <cuda_bf16.h>
#include <cstdint>

// x: [32,2048] int32 ids in [0,100000); W: [256,100000] f32 (EMBED-major);
// b: [256] f32; out: [65536,256] f32 = W[:, x[t]] + b.
//
// K1 (persistent, 256 CTAs): hist+rank -> 2-level parallel scan (consume-
//     and-zero bins) -> atomic-free scatter. 4 grid barriers, all phases
//     parallel across the grid (no single-CTA stall).
// K2 (grid 4096): proven gather: 32 sorted tokens x 128 dims per CTA,
//     coalesced strided LDG -> STS.128 tile (stride 132) -> LDS.128+bias ->
//     STG.128 evict-first contiguous rows.
static constexpr int VOCAB = 100000;
static constexpr int EMBED = 256;
static constexpr int NTOK  = 32 * 2048;            // 65536
static constexpr int NBINS = (VOCAB + 31) / 32;    // 3125
static constexpr int HDIM  = 128;
static constexpr int TSTR  = 132;
static constexpr int SORT_CTAS = 256;              // 256*256 = 1 thr/token

__device__ int  g_bins[NBINS];     // zero at load; scan re-zeroes each launch
__device__ int  g_offs[NBINS];
__device__ int  g_rank[NTOK];
__device__ int2 g_sorted[NTOK];
__device__ int  g_cta_sum[SORT_CTAS];
__device__ int  g_cta_base[SORT_CTAS];
__device__ unsigned          g_bar_count[4];
__device__ volatile unsigned g_bar_flag[4];
__device__ unsigned          g_done;

__device__ __forceinline__ int clamp_id(int v) {
    return min(max(v, 0), VOCAB - 1);
}

// Two-phase grid barrier; safe: 256 small CTAs are always co-resident.
__device__ __forceinline__ void grid_barrier(int b) {
    __syncthreads();
    if (threadIdx.x == 0) {
        __threadfence();
        unsigned v = atomicAdd(&g_bar_count[b], 1);
        if (v == SORT_CTAS - 1) {
            __threadfence();
            g_bar_flag[b] = 1;
        } else {
            while (g_bar_flag[b] == 0) __nanosleep(32);
        }
        __threadfence();
    }
    __syncthreads();
}

// ---- K1: persistent sort (hist+rank, 2-level scan, scatter) --------------
__global__ __launch_bounds__(256) void sort_kernel(const int* __restrict__ x)
{
    __shared__ int sbuf[256];
    const int tid  = threadIdx.x;
    const int gtid = blockIdx.x * 256 + tid;       // == token id (65536 thr)

    // Phase A: histogram + per-token rank
    const int v = clamp_id(__ldg(&x[gtid]));
    g_rank[gtid] = atomicAdd(&g_bins[v >> 5], 1);
    grid_barrier(0);

    // Phase B1: every CTA scans its 256-bin slice (consume-and-zero)
    const int idx = gtid;                          // bin index for this thread
    int c = (idx < NBINS) ? __ldcg(&g_bins[idx]) : 0;
    if (idx < NBINS) __stcg(&g_bins[idx], 0);      // restore invariant
    sbuf[tid] = c;
    __syncthreads();
    for (int off = 1; off < 256; off <<= 1) {      // Hillis-Steele inclusive
        int t = (tid >= off) ? sbuf[tid - off] : 0;
        __syncthreads();
        sbuf[tid] += t;
        __syncthreads();
    }
    const int excl = sbuf[tid] - c;                // exclusive within slice
    if (tid == 255) __stcg(&g_cta_sum[blockIdx.x], sbuf[255]);
    grid_barrier(1);

    // Phase B2: CTA0 scans the 256 slice totals
    if (blockIdx.x == 0) {
        int s = __ldcg(&g_cta_sum[tid]);
        sbuf[tid] = s;
        __syncthreads();
        for (int off = 1; off < 256; off <<= 1) {
            int t = (tid >= off) ? sbuf[tid - off] : 0;
            __syncthreads();
            sbuf[tid] += t;
            __syncthreads();
        }
        __stcg(&g_cta_base[tid], sbuf[tid] - s);   // exclusive
    }
    grid_barrier(2);

    // Phase B3: apply base -> final bin offsets
    if (idx < NBINS)
        __stcg(&g_offs[idx], __ldcg(&g_cta_base[blockIdx.x]) + excl);
    grid_barrier(3);

    // Phase C: atomic-free scatter (rank written by this same thread in A)
    const int pos = __ldcg(&g_offs[v >> 5]) + g_rank[gtid];
    __stcg(&g_sorted[pos], make_int2(v, gtid));

    // Reset barrier state for next graph replay (last CTA to finish)
    __syncthreads();
    if (tid == 0) {
        unsigned d = atomicAdd(&g_done, 1);
        if (d == SORT_CTAS - 1) {
            g_bar_count[0] = g_bar_count[1] = g_bar_count[2] = g_bar_count[3] = 0;
            g_bar_flag[0] = g_bar_flag[1] = g_bar_flag[2] = g_bar_flag[3] = 0;
            g_done = 0;
            __threadfence();
        }
    }
}

// ---- K2: gather, 32 tokens x 128 dims per CTA (proven R6 form) ----------
__global__ __launch_bounds__(256) void gather_kernel(
    const float* __restrict__ W,
    const float* __restrict__ bias,
    float*       __restrict__ out)
{
    __shared__ __align__(16) float tile[32][TSTR];
    __shared__ int s_id[32], s_tok[32];

    const int tid   = threadIdx.x;
    const int group = blockIdx.x >> 1;
    const int half  = blockIdx.x & 1;
    const int dim0  = half * HDIM;

    if (tid < 32) {
        int2 p = g_sorted[group * 32 + tid];
        s_id[tid]  = p.x;
        s_tok[tid] = p.y;
    }
    __syncthreads();

    const int w = tid >> 5;          // warp -> dims [16w,16w+16) of half
    const int l = tid & 31;          // lane -> sorted token

    const int vid = s_id[l];
    const float* wp = W + (size_t)(dim0 + w * 16) * VOCAB + (size_t)vid;
    float rr[16];
#pragma unroll
    for (int j = 0; j < 16; ++j)
        rr[j] = __ldg(wp + (size_t)j * VOCAB);     // coalesced via sort

#pragma unroll
    for (int j = 0; j < 4; ++j) {
        float4 v4 = make_float4(rr[4*j], rr[4*j+1], rr[4*j+2], rr[4*j+3]);
        *reinterpret_cast<float4*>(&tile[l][w * 16 + 4 * j]) = v4;
    }
    __syncthreads();

    const float4 bv = __ldg(reinterpret_cast<const float4*>(bias) + half * 32 + l);
#pragma unroll
    for (int i = 0; i < 4; ++i) {
        const int t    = w * 4 + i;
        const int orig = s_tok[t];
        float4 v4 = *reinterpret_cast<const float4*>(&tile[t][4 * l]);
        v4.x += bv.x; v4.y += bv.y; v4.z += bv.z; v4.w += bv.w;
        __stcs(reinterpret_cast<float4*>(out + (size_t)orig * EMBED + dim0) + l, v4);
    }
}

extern "C" void kernel_launch(void* const* d_in, const int* in_sizes, int n_in,
                              void* d_out, int out_size)
{
    const int*   x    = (const int*)d_in[0];
    const float* W    = (const float*)d_in[1];
    const float* bias = (const float*)d_in[2];
    float*       out  = (float*)d_out;

    sort_kernel<<<SORT_CTAS, 256>>>(x);
    gather_kernel<<<(NTOK / 32) * 2, 256>>>(W, bias, out);
}

// round 11
// speedup vs baseline: 1.1465x; 1.1465x over previous
#include <cuda_runtime.h>
#include <cuda_bf16.h>
#include <cstdint>

// x: [32,2048] int32 ids in [0,100000); W: [256,100000] f32 (EMBED-major);
// b: [256] f32; out: [65536,256] f32 = W[:, x[t]] + b.
//
// K1 hist_rank : 4 tok/thread (int4), rank[t]=atomicAdd(bins[id>>5],1) x4 ILP
// K2 scan      : 1 CTA, shuffle-based scan of 3125 bins; consume-and-zero
// K3 scatter   : 4 tok/thread, atomic-free: sorted[offs+rank] = {id,t}
// K4 gather    : 32 sorted tokens x 128 dims per CTA; coalesced strided LDG
//                -> STS.128 tile (stride 132, conflict-free) -> LDS.128+bias
//                -> __stwt STG.128 (write-through: keep L2 for W across
//                   graph replays; out is write-once streaming).
static constexpr int VOCAB = 100000;
static constexpr int EMBED = 256;
static constexpr int NTOK  = 32 * 2048;            // 65536
static constexpr int NBINS = (VOCAB + 31) / 32;    // 3125
static constexpr int HDIM  = 128;
static constexpr int TSTR  = 132;

__device__ int  g_bins[NBINS];     // zero at load; scan re-zeroes each launch
__device__ int  g_offs[NBINS];
__device__ int  g_rank[NTOK];
__device__ int2 g_sorted[NTOK];

__device__ __forceinline__ int clamp_id(int v) {
    return min(max(v, 0), VOCAB - 1);
}

// ---- K1: histogram + rank, 4 tokens/thread (ILP on atomic returns) ------
__global__ __launch_bounds__(256) void hist_rank_kernel(const int* __restrict__ x) {
    const int t0 = (blockIdx.x * 256 + threadIdx.x) * 4;
    const int4 xv = *reinterpret_cast<const int4*>(x + t0);
    int v0 = clamp_id(xv.x), v1 = clamp_id(xv.y);
    int v2 = clamp_id(xv.z), v3 = clamp_id(xv.w);
    int4 r;
    r.x = atomicAdd(&g_bins[v0 >> 5], 1);          // 4 independent atomics
    r.y = atomicAdd(&g_bins[v1 >> 5], 1);
    r.z = atomicAdd(&g_bins[v2 >> 5], 1);
    r.w = atomicAdd(&g_bins[v3 >> 5], 1);
    *reinterpret_cast<int4*>(g_rank + t0) = r;
}

// ---- K2: single-CTA scan, shuffle-based (2 __syncthreads total) ----------
__global__ __launch_bounds__(1024) void scan_kernel() {
    __shared__ int warp_tot[32];
    const int tid  = threadIdx.x;
    const int lane = tid & 31;
    const int wid  = tid >> 5;

    // thread handles bins [4tid, 4tid+4): contiguous, coalesced
    int c[4]; int s = 0;
#pragma unroll
    for (int k = 0; k < 4; ++k) {
        int idx = tid * 4 + k;
        c[k] = (idx < NBINS) ? __ldcg(&g_bins[idx]) : 0;
        if (idx < NBINS) __stcg(&g_bins[idx], 0);  // restore invariant
        s += c[k];
    }
    // warp-inclusive scan of per-thread sums
    int incl = s;
#pragma unroll
    for (int off = 1; off < 32; off <<= 1) {
        int t = __shfl_up_sync(0xffffffff, incl, off);
        if (lane >= off) incl += t;
    }
    if (lane == 31) warp_tot[wid] = incl;
    __syncthreads();
    if (wid == 0) {                                // scan 32 warp totals
        int wv = warp_tot[lane];
        int wi = wv;
#pragma unroll
        for (int off = 1; off < 32; off <<= 1) {
            int t = __shfl_up_sync(0xffffffff, wi, off);
            if (lane >= off) wi += t;
        }
        warp_tot[lane] = wi - wv;                  // exclusive base per warp
    }
    __syncthreads();
    int base = warp_tot[wid] + (incl - s);         // exclusive for this thread
#pragma unroll
    for (int k = 0; k < 4; ++k) {
        int idx = tid * 4 + k;
        if (idx < NBINS) __stcg(&g_offs[idx], base);
        base += c[k];
    }
}

// ---- K3: atomic-free scatter, 4 tokens/thread ----------------------------
__global__ __launch_bounds__(256) void scatter_kernel(const int* __restrict__ x) {
    const int t0 = (blockIdx.x * 256 + threadIdx.x) * 4;
    const int4 xv = *reinterpret_cast<const int4*>(x + t0);
    const int4 rv = *reinterpret_cast<const int4*>(g_rank + t0);
    int v[4] = { clamp_id(xv.x), clamp_id(xv.y), clamp_id(xv.z), clamp_id(xv.w) };
    int rk[4] = { rv.x, rv.y, rv.z, rv.w };
    int of[4];
#pragma unroll
    for (int k = 0; k < 4; ++k) of[k] = __ldcg(&g_offs[v[k] >> 5]);  // 4-deep MLP
#pragma unroll
    for (int k = 0; k < 4; ++k)
        __stcg(&g_sorted[of[k] + rk[k]], make_int2(v[k], t0 + k));
}

// ---- K4: gather, 32 tokens x 128 dims per CTA ----------------------------
__global__ __launch_bounds__(256) void gather_kernel(
    const float* __restrict__ W,
    const float* __restrict__ bias,
    float*       __restrict__ out)
{
    __shared__ __align__(16) float tile[32][TSTR];
    __shared__ int s_id[32], s_tok[32];

    const int tid   = threadIdx.x;
    const int group = blockIdx.x >> 1;
    const int half  = blockIdx.x & 1;
    const int dim0  = half * HDIM;

    if (tid < 32) {
        int2 p = g_sorted[group * 32 + tid];
        s_id[tid]  = p.x;
        s_tok[tid] = p.y;
    }
    __syncthreads();

    const int w = tid >> 5;          // warp -> dims [16w,16w+16) of half
    const int l = tid & 31;          // lane -> sorted token

    const int vid = s_id[l];
    const float* wp = W + (size_t)(dim0 + w * 16) * VOCAB + (size_t)vid;
    float rr[16];
#pragma unroll
    for (int j = 0; j < 16; ++j)
        rr[j] = __ldg(wp + (size_t)j * VOCAB);     // coalesced via sort

#pragma unroll
    for (int j = 0; j < 4; ++j) {
        float4 v4 = make_float4(rr[4*j], rr[4*j+1], rr[4*j+2], rr[4*j+3]);
        *reinterpret_cast<float4*>(&tile[l][w * 16 + 4 * j]) = v4;
    }
    __syncthreads();

    const float4 bv = __ldg(reinterpret_cast<const float4*>(bias) + half * 32 + l);
#pragma unroll
    for (int i = 0; i < 4; ++i) {
        const int t    = w * 4 + i;
        const int orig = s_tok[t];
        float4 v4 = *reinterpret_cast<const float4*>(&tile[t][4 * l]);
        v4.x += bv.x; v4.y += bv.y; v4.z += bv.z; v4.w += bv.w;
        // write-through: don't let the 64MB output stream occupy L2
        __stwt(reinterpret_cast<float4*>(out + (size_t)orig * EMBED + dim0) + l, v4);
    }
}

extern "C" void kernel_launch(void* const* d_in, const int* in_sizes, int n_in,
                              void* d_out, int out_size)
{
    const int*   x    = (const int*)d_in[0];
    const float* W    = (const float*)d_in[1];
    const float* bias = (const float*)d_in[2];
    float*       out  = (float*)d_out;

    hist_rank_kernel<<<NTOK / 1024, 256>>>(x);     // 64 CTAs, 4 tok/thread
    scan_kernel<<<1, 1024>>>();
    scatter_kernel<<<NTOK / 1024, 256>>>(x);       // 64 CTAs, 4 tok/thread
    gather_kernel<<<(NTOK / 32) * 2, 256>>>(W, bias, out);
}